// round 14
// baseline (speedup 1.0000x reference)
#include <cuda_runtime.h>
#include <cuda_bf16.h>
#include <math_constants.h>
#include <cstdint>

// Problem constants
#define B_ 8
#define T_ 8192
#define L_ 256
#define D_ 512
#define H_ 8
// HD = 64, scale = 1/8

// ---------------- scratch (device globals; no allocs allowed) ----------------
__device__ __nv_bfloat16 g_qh [(size_t)B_ * L_ * D_],  g_ql [(size_t)B_ * L_ * D_];
__device__ __nv_bfloat16 g_kvh[(size_t)B_ * T_ * 2 * D_], g_kvl[(size_t)B_ * T_ * 2 * D_];
__device__ float         g_att[(size_t)B_ * L_ * D_];

__device__ __nv_bfloat16 g_wkv_h[1024 * 512], g_wkv_l[1024 * 512];   // Wkv^T split
__device__ __nv_bfloat16 g_wq_h [512 * 512],  g_wq_l [512 * 512];    // Wq^T split
__device__ __nv_bfloat16 g_wp_h [512 * 512],  g_wp_l [512 * 512];    // Wproj^T split

__device__ __forceinline__ uint32_t smem_u32(const void* p) {
    uint32_t a;
    asm("{ .reg .u64 t; cvta.to.shared.u64 t, %1; cvt.u32.u64 %0, t; }"
        : "=r"(a) : "l"(p));
    return a;
}

#define CP16(dst, src) \
    asm volatile("cp.async.cg.shared.global [%0], [%1], 16;" :: "r"(dst), "l"(src))
#define CP_COMMIT() asm volatile("cp.async.commit_group;" ::: "memory")
#define CP_WAIT(n)  asm volatile("cp.async.wait_group %0;" :: "n"(n) : "memory")

#define LDSM4(r, addr) \
    asm volatile("ldmatrix.sync.aligned.m8n8.x4.shared.b16 {%0,%1,%2,%3}, [%4];" \
        : "=r"((r)[0]), "=r"((r)[1]), "=r"((r)[2]), "=r"((r)[3]) : "r"(addr))
#define LDSM4T(r, addr) \
    asm volatile("ldmatrix.sync.aligned.m8n8.x4.trans.shared.b16 {%0,%1,%2,%3}, [%4];" \
        : "=r"((r)[0]), "=r"((r)[1]), "=r"((r)[2]), "=r"((r)[3]) : "r"(addr))

#define MMA16816(d, a, b0r, b1r) \
    asm volatile("mma.sync.aligned.m16n8k16.row.col.f32.bf16.bf16.f32 " \
        "{%0,%1,%2,%3}, {%4,%5,%6,%7}, {%8,%9}, {%0,%1,%2,%3};" \
        : "+f"((d)[0]), "+f"((d)[1]), "+f"((d)[2]), "+f"((d)[3]) \
        : "r"((a)[0]), "r"((a)[1]), "r"((a)[2]), "r"((a)[3]), "r"(b0r), "r"(b1r))

#define SWZ64(o)  ((o) ^ ((((o) >> 7) & 3) << 4))
#define SWZ128(o) ((o) ^ ((((o) >> 7) & 7) << 4))

// =============================================================================
// Weight split/transpose: W[K,N] fp32 -> Wt_hi/Wt_lo [N,K] bf16
// =============================================================================
__global__ void split_w(const float* __restrict__ W, __nv_bfloat16* __restrict__ Th,
                        __nv_bfloat16* __restrict__ Tl, int K, int N)
{
    int idx = blockIdx.x * blockDim.x + threadIdx.x;
    if (idx >= K * N) return;
    int k = idx / N, n = idx % N;
    float w = W[idx];
    __nv_bfloat16 h = __float2bfloat16_rn(w);
    float r = w - __bfloat162float(h);
    Th[(size_t)n * K + k] = h;
    Tl[(size_t)n * K + k] = __float2bfloat16_rn(r);
}

// =============================================================================
// Templated fused GEMM, 128 threads / 4 warps, CTA 64x256, warp 64x64, 2 CTA/SM.
// TWO_TERM=true : kv K-columns, grid (2,1024): 2-term, no Al anywhere, Ch only.
// TWO_TERM=false: kv V-columns + q, grid (2,1056): 3-term, Ch+Cl.
// B via 3-stage cp.async; A via LDG fp32 prefetch issued AFTER compute
// (pa regs dead during MMA phase; latency covered by co-resident CTA).
// smem: A bufs @0,@8192 (Ah 4K|Al 4K); B stages @16384+s*32768. Total 112KB.
// =============================================================================
#define GEMM_SMEM 114688

template<bool TWO_TERM>
__global__ __launch_bounds__(128, 2)
void gemm_tile(const float* __restrict__ x, const float* __restrict__ query,
               const __nv_bfloat16* __restrict__ wkvh, const __nv_bfloat16* __restrict__ wkvl,
               const __nv_bfloat16* __restrict__ wqh,  const __nv_bfloat16* __restrict__ wql,
               const float* __restrict__ bkv, const float* __restrict__ bq,
               __nv_bfloat16* __restrict__ kvh, __nv_bfloat16* __restrict__ kvl,
               __nv_bfloat16* __restrict__ qh,  __nv_bfloat16* __restrict__ ql,
               float cscale)
{
    const float* A;
    const __nv_bfloat16 *Bth, *Btl;
    const float* bias;
    __nv_bfloat16 *Ch, *Cl;
    float scale;
    int N, bm, bn;

    if (TWO_TERM) {
        // kv K-columns
        A = x; Bth = wkvh; Btl = wkvl; bias = bkv;
        Ch = kvh; Cl = nullptr; scale = 1.0f; N = 1024;
        bm = blockIdx.y * 64; bn = blockIdx.x * 256;
    } else {
        const bool isQ = (blockIdx.y >= 1024);
        A    = isQ ? query : x;
        Bth  = isQ ? wqh : wkvh;
        Btl  = isQ ? wql : wkvl;
        bias = isQ ? bq : bkv;
        Ch   = isQ ? qh : kvh;
        Cl   = isQ ? ql : kvl;
        scale = isQ ? cscale : 1.0f;
        N    = isQ ? 512 : 1024;
        bm   = (isQ ? (blockIdx.y - 1024) : blockIdx.y) * 64;
        bn   = (isQ ? 0 : 512) + blockIdx.x * 256;
    }
    const int K = 512;

    extern __shared__ char smem[];
    const uint32_t sbase = smem_u32(smem);
    const int tid  = threadIdx.x;
    const int lane = tid & 31;
    const int wn   = tid >> 5;

    float acc[4][8][4];
    #pragma unroll
    for (int i = 0; i < 4; i++)
        #pragma unroll
        for (int j = 0; j < 8; j++)
            #pragma unroll
            for (int k = 0; k < 4; k++) acc[i][j][k] = 0.f;

    const int nchunk = K >> 5;

    auto produceB = [&](int c, int s) {
        const uint32_t base = sbase + 16384 + (uint32_t)s * 32768;
        #pragma unroll
        for (int i = 0; i < 8; i++) {
            int idx = tid + i * 128;
            int n = idx >> 2, sg = idx & 3;
            uint32_t sw = SWZ64(n * 64 + sg * 16);
            const size_t gb = (size_t)(bn + n) * K + c * 32 + sg * 8;
            CP16(base + sw,         Bth + gb);
            CP16(base + 16384 + sw, Btl + gb);
        }
    };

    float4 pa[4];
    auto loadA = [&](int c) {
        #pragma unroll
        for (int i = 0; i < 4; i++) {
            int idx = tid + i * 128;
            int r = idx >> 3, k4 = idx & 7;
            pa[i] = *reinterpret_cast<const float4*>(
                A + (size_t)(bm + r) * K + c * 32 + k4 * 4);
        }
    };
    auto storeA = [&](int buf) {
        char* base = smem + buf * 8192;
        #pragma unroll
        for (int i = 0; i < 4; i++) {
            int idx = tid + i * 128;
            int r = idx >> 3, k4 = idx & 7;
            uint32_t sw = SWZ64(r * 64 + k4 * 8);
            float4 v = pa[i];
            __nv_bfloat162 h01 = __floats2bfloat162_rn(v.x, v.y);
            __nv_bfloat162 h23 = __floats2bfloat162_rn(v.z, v.w);
            *reinterpret_cast<uint2*>(base + sw) =
                make_uint2(*(uint32_t*)&h01, *(uint32_t*)&h23);
            if (!TWO_TERM) {
                float2 f01 = __bfloat1622float2(h01);
                float2 f23 = __bfloat1622float2(h23);
                __nv_bfloat162 l01 = __floats2bfloat162_rn(v.x - f01.x, v.y - f01.y);
                __nv_bfloat162 l23 = __floats2bfloat162_rn(v.z - f23.x, v.w - f23.y);
                *reinterpret_cast<uint2*>(base + 4096 + sw) =
                    make_uint2(*(uint32_t*)&l01, *(uint32_t*)&l23);
            }
        }
    };

    const uint32_t arow  = (lane & 15);
    const uint32_t aoffb = arow * 64 + ((lane >> 4) << 4);
    const uint32_t axor  = ((arow >> 1) & 3) << 4;
    const uint32_t blrow = (lane & 7) + ((lane >> 4) << 3);
    const uint32_t bseg  = ((uint32_t)((lane >> 3) & 1)) << 4;

    auto compute = [&](int c) {
        const uint32_t sa = sbase + (uint32_t)(c & 1) * 8192;
        const uint32_t sbB = sbase + 16384 + (uint32_t)(c % 3) * 32768;
        #pragma unroll
        for (int ks = 0; ks < 2; ks++) {
            uint32_t Ah[4][4], Al[4][4];
            #pragma unroll
            for (int mt = 0; mt < 4; mt++) {
                uint32_t addr = (sa + aoffb + mt * 1024 + ks * 32) ^ axor;
                LDSM4(Ah[mt], addr);
                if (!TWO_TERM) LDSM4(Al[mt], addr + 4096);
            }
            #pragma unroll
            for (int np = 0; np < 4; np++) {
                const uint32_t brow = wn * 64 + np * 16 + blrow;
                uint32_t off = brow * 64 + bseg + ks * 32;
                uint32_t addr = sbB + (off ^ (((brow >> 1) & 3) << 4));
                uint32_t Bh[4], Bl[4];
                LDSM4(Bh, addr);
                LDSM4(Bl, addr + 16384);
                float* d;
                #pragma unroll
                for (int mt = 0; mt < 4; mt++) {
                    d = acc[mt][2 * np];     MMA16816(d, Ah[mt], Bh[0], Bh[1]);
                    d = acc[mt][2 * np + 1]; MMA16816(d, Ah[mt], Bh[2], Bh[3]);
                }
                #pragma unroll
                for (int mt = 0; mt < 4; mt++) {
                    d = acc[mt][2 * np];     MMA16816(d, Ah[mt], Bl[0], Bl[1]);
                    d = acc[mt][2 * np + 1]; MMA16816(d, Ah[mt], Bl[2], Bl[3]);
                }
                if (!TWO_TERM) {
                    #pragma unroll
                    for (int mt = 0; mt < 4; mt++) {
                        d = acc[mt][2 * np];     MMA16816(d, Al[mt], Bh[0], Bh[1]);
                        d = acc[mt][2 * np + 1]; MMA16816(d, Al[mt], Bh[2], Bh[3]);
                    }
                }
            }
        }
    };

    produceB(0, 0); CP_COMMIT();
    produceB(1, 1); CP_COMMIT();
    loadA(0);
    storeA(0);
    for (int c = 0; c < nchunk; c++) {
        CP_WAIT(1);
        __syncthreads();   // publishes storeA(c) and B stage c; guards reuse
        if (c + 2 < nchunk) { produceB(c + 2, (c + 2) % 3); CP_COMMIT(); }
        compute(c);
        if (c + 1 < nchunk) {
            loadA(c + 1);            // pa live only across storeA (reg relief)
            storeA((c + 1) & 1);
        }
    }

    // ---- epilogue: bf16 hi/lo (Cl skipped for 2-term) ----
    #pragma unroll
    for (int nt = 0; nt < 8; nt++) {
        const int ncol = bn + wn * 64 + nt * 8 + 2 * (lane & 3);
        const float2 bb = *reinterpret_cast<const float2*>(bias + ncol);
        #pragma unroll
        for (int mt = 0; mt < 4; mt++) {
            const int m0 = bm + mt * 16 + (lane >> 2);
            float v0 = (acc[mt][nt][0] + bb.x) * scale;
            float v1 = (acc[mt][nt][1] + bb.y) * scale;
            float v2 = (acc[mt][nt][2] + bb.x) * scale;
            float v3 = (acc[mt][nt][3] + bb.y) * scale;
            __nv_bfloat162 h01 = __floats2bfloat162_rn(v0, v1);
            __nv_bfloat162 h23 = __floats2bfloat162_rn(v2, v3);
            *reinterpret_cast<uint32_t*>(Ch + (size_t)m0 * N + ncol) = *(uint32_t*)&h01;
            *reinterpret_cast<uint32_t*>(Ch + (size_t)(m0 + 8) * N + ncol) = *(uint32_t*)&h23;
            if (!TWO_TERM) {
                float2 f01 = __bfloat1622float2(h01);
                float2 f23 = __bfloat1622float2(h23);
                __nv_bfloat162 l01 = __floats2bfloat162_rn(v0 - f01.x, v1 - f01.y);
                __nv_bfloat162 l23 = __floats2bfloat162_rn(v2 - f23.x, v3 - f23.y);
                *reinterpret_cast<uint32_t*>(Cl + (size_t)m0 * N + ncol) = *(uint32_t*)&l01;
                *reinterpret_cast<uint32_t*>(Cl + (size_t)(m0 + 8) * N + ncol) = *(uint32_t*)&l23;
            }
        }
    }
}

// =============================================================================
// proj GEMM: 64x128 CTA / 128 threads / 2 CTAs/SM (R12-proven geometry).
// out = att(fp32) @ Wp^T + bias, 3-term, fp32 out. grid (4, 32) = 128 CTAs.
// Stage = 24KB: Ah@0(4K) Al@4096(4K) Bh@8192(8K) Bl@16384(8K); 2 stages = 48KB.
// =============================================================================
#define PROJ_SMEM 49152

__global__ __launch_bounds__(128, 2)
void gemm_proj(const float* __restrict__ A,
               const __nv_bfloat16* __restrict__ Bth, const __nv_bfloat16* __restrict__ Btl,
               const float* __restrict__ bias, float* __restrict__ Cf,
               int M, int N, int K)
{
    extern __shared__ char smem[];
    const uint32_t sbase = smem_u32(smem);
    const int tid  = threadIdx.x;
    const int lane = tid & 31;
    const int wn   = tid >> 5;
    const int bm = blockIdx.y * 64;
    const int bn = blockIdx.x * 128;

    float acc[4][4][4];
    #pragma unroll
    for (int i = 0; i < 4; i++)
        #pragma unroll
        for (int j = 0; j < 4; j++)
            #pragma unroll
            for (int k = 0; k < 4; k++) acc[i][j][k] = 0.f;

    const int nchunk = K >> 5;
    float4 pa[4];
    uint4  pbh[4], pbl[4];

    auto loadg = [&](int c) {
        #pragma unroll
        for (int i = 0; i < 4; i++) {
            int idx = tid + i * 128;
            int r = idx >> 3, k4 = idx & 7;
            pa[i] = *reinterpret_cast<const float4*>(
                A + (size_t)(bm + r) * K + c * 32 + k4 * 4);
        }
        #pragma unroll
        for (int i = 0; i < 4; i++) {
            int idx = tid + i * 128;
            int n = idx >> 2, s = idx & 3;
            const size_t go = (size_t)(bn + n) * K + c * 32 + s * 8;
            pbh[i] = *reinterpret_cast<const uint4*>(Bth + go);
            pbl[i] = *reinterpret_cast<const uint4*>(Btl + go);
        }
    };

    auto storeS = [&](int buf) {
        char* base = smem + buf * 24576;
        #pragma unroll
        for (int i = 0; i < 4; i++) {
            int idx = tid + i * 128;
            int r = idx >> 3, k4 = idx & 7;
            uint32_t sw = SWZ64(r * 64 + k4 * 8);
            float4 v = pa[i];
            __nv_bfloat162 h01 = __floats2bfloat162_rn(v.x, v.y);
            __nv_bfloat162 h23 = __floats2bfloat162_rn(v.z, v.w);
            float2 f01 = __bfloat1622float2(h01);
            float2 f23 = __bfloat1622float2(h23);
            __nv_bfloat162 l01 = __floats2bfloat162_rn(v.x - f01.x, v.y - f01.y);
            __nv_bfloat162 l23 = __floats2bfloat162_rn(v.z - f23.x, v.w - f23.y);
            *reinterpret_cast<uint2*>(base + sw) =
                make_uint2(*(uint32_t*)&h01, *(uint32_t*)&h23);
            *reinterpret_cast<uint2*>(base + 4096 + sw) =
                make_uint2(*(uint32_t*)&l01, *(uint32_t*)&l23);
        }
        #pragma unroll
        for (int i = 0; i < 4; i++) {
            int idx = tid + i * 128;
            int n = idx >> 2, s = idx & 3;
            uint32_t sw = SWZ64(n * 64 + s * 16);
            *reinterpret_cast<uint4*>(base + 8192 + sw)  = pbh[i];
            *reinterpret_cast<uint4*>(base + 16384 + sw) = pbl[i];
        }
    };

    const uint32_t arow  = (lane & 15);
    const uint32_t aoffb = arow * 64 + ((lane >> 4) << 4);
    const uint32_t axor  = ((arow >> 1) & 3) << 4;
    const uint32_t brow  = wn * 32 + (lane & 7) + ((lane >> 4) << 3);
    const uint32_t boffb = brow * 64 + (((lane >> 3) & 1) << 4);
    const uint32_t bxor  = ((brow >> 1) & 3) << 4;

    auto compute = [&](int buf) {
        const uint32_t sa = sbase + buf * 24576;
        #pragma unroll
        for (int ks = 0; ks < 2; ks++) {
            uint32_t Ah[4][4], Al[4][4];
            #pragma unroll
            for (int mt = 0; mt < 4; mt++) {
                uint32_t addr = (sa + aoffb + mt * 1024 + ks * 32) ^ axor;
                LDSM4(Ah[mt], addr);
                LDSM4(Al[mt], addr + 4096);
            }
            uint32_t Bh[2][4], Bl[2][4];
            #pragma unroll
            for (int np = 0; np < 2; np++) {
                uint32_t addr = (sa + 8192 + boffb + np * 1024 + ks * 32) ^ bxor;
                LDSM4(Bh[np], addr);
                LDSM4(Bl[np], addr + 8192);
            }
            #pragma unroll
            for (int mt = 0; mt < 4; mt++)
                #pragma unroll
                for (int nt = 0; nt < 4; nt++) {
                    const int np = nt >> 1, bi = (nt & 1) * 2;
                    MMA16816(acc[mt][nt], Ah[mt], Bh[np][bi], Bh[np][bi + 1]);
                }
            #pragma unroll
            for (int mt = 0; mt < 4; mt++)
                #pragma unroll
                for (int nt = 0; nt < 4; nt++) {
                    const int np = nt >> 1, bi = (nt & 1) * 2;
                    MMA16816(acc[mt][nt], Ah[mt], Bl[np][bi], Bl[np][bi + 1]);
                }
            #pragma unroll
            for (int mt = 0; mt < 4; mt++)
                #pragma unroll
                for (int nt = 0; nt < 4; nt++) {
                    const int np = nt >> 1, bi = (nt & 1) * 2;
                    MMA16816(acc[mt][nt], Al[mt], Bh[np][bi], Bh[np][bi + 1]);
                }
        }
    };

    loadg(0);
    storeS(0);
    __syncthreads();
    for (int c = 0; c < nchunk; c++) {
        if (c + 1 < nchunk) loadg(c + 1);
        compute(c & 1);
        if (c + 1 < nchunk) {
            storeS((c + 1) & 1);
            __syncthreads();
        }
    }

    #pragma unroll
    for (int nt = 0; nt < 4; nt++) {
        const int ncol = bn + wn * 32 + nt * 8 + 2 * (lane & 3);
        const float2 bb = *reinterpret_cast<const float2*>(bias + ncol);
        #pragma unroll
        for (int mt = 0; mt < 4; mt++) {
            const int m0 = bm + mt * 16 + (lane >> 2);
            *reinterpret_cast<float2*>(Cf + (size_t)m0 * N + ncol) =
                make_float2(acc[mt][nt][0] + bb.x, acc[mt][nt][1] + bb.y);
            *reinterpret_cast<float2*>(Cf + (size_t)(m0 + 8) * N + ncol) =
                make_float2(acc[mt][nt][2] + bb.x, acc[mt][nt][3] + bb.y);
        }
    }
}

// =============================================================================
// HMMA flash attention (R9-proven, unchanged). 128 threads / 4 warps / 64 Q-rows;
// grid 256; 2 CTAs/SM. QK = (Qh+Ql)*Kh; PV = 3-term. Stage 24KB ring @0/24K/48K;
// Q hi @73728, lo @81920. smem = 88KB.
// =============================================================================
#define ATTN_SMEM 90112

__global__ __launch_bounds__(128, 2)
void attn2(const __nv_bfloat16* __restrict__ qsh, const __nv_bfloat16* __restrict__ qsl,
           const __nv_bfloat16* __restrict__ kvh, const __nv_bfloat16* __restrict__ kvl,
           float* __restrict__ attf)
{
    extern __shared__ char smem[];
    const uint32_t sb = smem_u32(smem);
    const int tid = threadIdx.x, lane = tid & 31, warp = tid >> 5;
    const int bid = blockIdx.x;
    const int lt = bid & 3;
    const int h  = (bid >> 2) & 7;
    const int b  = bid >> 5;
    const int l0 = lt * 64;

    #pragma unroll
    for (int i = 0; i < 4; i++) {
        int idx = tid + i * 128;
        int r = idx >> 3, sg = idx & 7;
        uint32_t sw = SWZ128(r * 128 + sg * 16);
        size_t g = (size_t)(b * L_ + l0 + r) * 512 + h * 64 + sg * 8;
        CP16(sb + 73728 + sw, qsh + g);
        CP16(sb + 81920 + sw, qsl + g);
    }
    CP_COMMIT();
    CP_WAIT(0);
    __syncthreads();

    uint32_t Qh[4][4], Ql[4][4];
    {
        const int arow = warp * 16 + (lane & 15);
        const uint32_t abase = sb + 73728 + arow * 128;
        const uint32_t axor = (arow & 7) << 4;
        #pragma unroll
        for (int kc = 0; kc < 4; kc++) {
            uint32_t o = ((((uint32_t)(lane >> 4) << 4) + kc * 32)) ^ axor;
            LDSM4(Qh[kc], abase + o);
            LDSM4(Ql[kc], abase + 8192 + o);
        }
    }
    __syncthreads();

    auto produce = [&](int c, int s) {
        const uint32_t base = sb + (uint32_t)s * 24576;
        #pragma unroll
        for (int i = 0; i < 4; i++) {
            int idx = tid + i * 128;
            int r = idx >> 3, sg = idx & 7;
            uint32_t sw = SWZ128(r * 128 + sg * 16);
            size_t g = (size_t)(b * T_ + c * 64 + r) * 1024 + h * 64 + sg * 8;
            CP16(base + sw,         kvh + g);
            CP16(base + 8192 + sw,  kvh + g + 512);
            CP16(base + 16384 + sw, kvl + g + 512);
        }
    };
    produce(0, 0); CP_COMMIT();
    produce(1, 1); CP_COMMIT();

    float mrow[2] = { -CUDART_INF_F, -CUDART_INF_F };
    float lsum[2] = { 0.f, 0.f };
    float O[8][4];
    #pragma unroll
    for (int i = 0; i < 8; i++)
        #pragma unroll
        for (int j = 0; j < 4; j++) O[i][j] = 0.f;

    const int klrow = (lane & 7) + ((lane >> 4) << 3);
    const uint32_t kseg = ((uint32_t)((lane >> 3) & 1)) << 4;
    const int vlrow = (lane & 7) + (((lane >> 3) & 1) << 3);
    const int vseg_half = lane >> 4;

    int bufc = 0;
    for (int c = 0; c < T_ / 64; c++) {
        CP_WAIT(1);
        __syncthreads();
        const uint32_t kb = sb + (uint32_t)bufc * 24576;

        float S[8][4];
        #pragma unroll
        for (int i = 0; i < 8; i++)
            #pragma unroll
            for (int j = 0; j < 4; j++) S[i][j] = 0.f;

        #pragma unroll
        for (int npp = 0; npp < 2; npp++) {
            #pragma unroll
            for (int kc = 0; kc < 4; kc++) {
                const int brow0 = (2 * npp) * 16 + klrow;
                const int brow1 = (2 * npp + 1) * 16 + klrow;
                uint32_t a0 = kb + brow0 * 128 + ((kseg + kc * 32) ^ ((brow0 & 7) << 4));
                uint32_t a1 = kb + brow1 * 128 + ((kseg + kc * 32) ^ ((brow1 & 7) << 4));
                uint32_t Bh0[4], Bh1[4];
                LDSM4(Bh0, a0);
                LDSM4(Bh1, a1);
                float* s0 = S[4 * npp];     float* s1 = S[4 * npp + 1];
                float* s2 = S[4 * npp + 2]; float* s3 = S[4 * npp + 3];
                MMA16816(s0, Qh[kc], Bh0[0], Bh0[1]);
                MMA16816(s1, Qh[kc], Bh0[2], Bh0[3]);
                MMA16816(s2, Qh[kc], Bh1[0], Bh1[1]);
                MMA16816(s3, Qh[kc], Bh1[2], Bh1[3]);
                MMA16816(s0, Ql[kc], Bh0[0], Bh0[1]);
                MMA16816(s1, Ql[kc], Bh0[2], Bh0[3]);
                MMA16816(s2, Ql[kc], Bh1[0], Bh1[1]);
                MMA16816(s3, Ql[kc], Bh1[2], Bh1[3]);
            }
        }

        float mxA = -CUDART_INF_F, mxB = -CUDART_INF_F;
        #pragma unroll
        for (int nt = 0; nt < 8; nt++) {
            mxA = fmaxf(mxA, fmaxf(S[nt][0], S[nt][1]));
            mxB = fmaxf(mxB, fmaxf(S[nt][2], S[nt][3]));
        }
        #pragma unroll
        for (int o = 1; o <= 2; o <<= 1) {
            mxA = fmaxf(mxA, __shfl_xor_sync(0xffffffffu, mxA, o));
            mxB = fmaxf(mxB, __shfl_xor_sync(0xffffffffu, mxB, o));
        }
        const float mnA = fmaxf(mrow[0], mxA);
        const float mnB = fmaxf(mrow[1], mxB);
        const float alphaA = exp2f(mrow[0] - mnA);
        const float alphaB = exp2f(mrow[1] - mnB);
        mrow[0] = mnA; mrow[1] = mnB;

        uint32_t Ph[4][4], Pl[4][4];
        float sumA = 0.f, sumB = 0.f;
        #pragma unroll
        for (int nt = 0; nt < 8; nt++) {
            float p0 = exp2f(S[nt][0] - mnA);
            float p1 = exp2f(S[nt][1] - mnA);
            float p2 = exp2f(S[nt][2] - mnB);
            float p3 = exp2f(S[nt][3] - mnB);
            sumA += p0 + p1; sumB += p2 + p3;
            __nv_bfloat162 hA = __floats2bfloat162_rn(p0, p1);
            __nv_bfloat162 hB = __floats2bfloat162_rn(p2, p3);
            float2 fA = __bfloat1622float2(hA);
            float2 fB = __bfloat1622float2(hB);
            __nv_bfloat162 lA = __floats2bfloat162_rn(p0 - fA.x, p1 - fA.y);
            __nv_bfloat162 lB = __floats2bfloat162_rn(p2 - fB.x, p3 - fB.y);
            const int kc = nt >> 1, ri = (nt & 1) * 2;
            Ph[kc][ri]     = *(uint32_t*)&hA;
            Ph[kc][ri + 1] = *(uint32_t*)&hB;
            Pl[kc][ri]     = *(uint32_t*)&lA;
            Pl[kc][ri + 1] = *(uint32_t*)&lB;
        }
        #pragma unroll
        for (int o = 1; o <= 2; o <<= 1) {
            sumA += __shfl_xor_sync(0xffffffffu, sumA, o);
            sumB += __shfl_xor_sync(0xffffffffu, sumB, o);
        }
        lsum[0] = lsum[0] * alphaA + sumA;
        lsum[1] = lsum[1] * alphaB + sumB;
        #pragma unroll
        for (int nt = 0; nt < 8; nt++) {
            O[nt][0] *= alphaA; O[nt][1] *= alphaA;
            O[nt][2] *= alphaB; O[nt][3] *= alphaB;
        }

        #pragma unroll
        for (int kc = 0; kc < 4; kc++) {
            const int vrow = kc * 16 + vlrow;
            const uint32_t vbase = kb + 8192 + vrow * 128;
            const uint32_t vxor = (vrow & 7) << 4;
            #pragma unroll
            for (int ngp = 0; ngp < 2; ngp++) {
                uint32_t o0 = ((uint32_t)((4 * ngp + vseg_half) << 4)) ^ vxor;
                uint32_t o1 = ((uint32_t)((4 * ngp + 2 + vseg_half) << 4)) ^ vxor;
                uint32_t Vh0[4], Vl0[4], Vh1[4], Vl1[4];
                LDSM4T(Vh0, vbase + o0); LDSM4T(Vl0, vbase + 8192 + o0);
                LDSM4T(Vh1, vbase + o1); LDSM4T(Vl1, vbase + 8192 + o1);
                float* d0 = O[4 * ngp];     float* d1 = O[4 * ngp + 1];
                float* d2 = O[4 * ngp + 2]; float* d3 = O[4 * ngp + 3];
                MMA16816(d0, Ph[kc], Vh0[0], Vh0[1]);
                MMA16816(d1, Ph[kc], Vh0[2], Vh0[3]);
                MMA16816(d2, Ph[kc], Vh1[0], Vh1[1]);
                MMA16816(d3, Ph[kc], Vh1[2], Vh1[3]);
                MMA16816(d0, Ph[kc], Vl0[0], Vl0[1]);
                MMA16816(d1, Ph[kc], Vl0[2], Vl0[3]);
                MMA16816(d2, Ph[kc], Vl1[0], Vl1[1]);
                MMA16816(d3, Ph[kc], Vl1[2], Vl1[3]);
                MMA16816(d0, Pl[kc], Vh0[0], Vh0[1]);
                MMA16816(d1, Pl[kc], Vh0[2], Vh0[3]);
                MMA16816(d2, Pl[kc], Vh1[0], Vh1[1]);
                MMA16816(d3, Pl[kc], Vh1[2], Vh1[3]);
            }
        }

        if (c + 2 < T_ / 64) produce(c + 2, (bufc + 2) % 3);
        CP_COMMIT();
        bufc = (bufc + 1) % 3;
    }
    CP_WAIT(0);

    const float invA = 1.0f / lsum[0];
    const float invB = 1.0f / lsum[1];
    const int rowA = b * L_ + l0 + warp * 16 + (lane >> 2);
    #pragma unroll
    for (int nt = 0; nt < 8; nt++) {
        const int col = h * 64 + nt * 8 + (lane & 3) * 2;
        *reinterpret_cast<float2*>(attf + (size_t)rowA * D_ + col) =
            make_float2(O[nt][0] * invA, O[nt][1] * invA);
        *reinterpret_cast<float2*>(attf + (size_t)(rowA + 8) * D_ + col) =
            make_float2(O[nt][2] * invB, O[nt][3] * invB);
    }
}

// =============================================================================
// launch
// =============================================================================
extern "C" void kernel_launch(void* const* d_in, const int* in_sizes, int n_in,
                              void* d_out, int out_size)
{
    const float* x     = (const float*)d_in[0];
    const float* query = (const float*)d_in[1];
    const float* Wq    = (const float*)d_in[2];
    const float* bq    = (const float*)d_in[3];
    const float* Wkv   = (const float*)d_in[4];
    const float* bkv   = (const float*)d_in[5];
    const float* Wproj = (const float*)d_in[6];
    const float* bproj = (const float*)d_in[7];
    float* out = (float*)d_out;

    __nv_bfloat16 *qh, *ql, *kvh, *kvl;
    float* att;
    __nv_bfloat16 *wkvh, *wkvl, *wqh, *wql, *wph, *wpl;
    cudaGetSymbolAddress((void**)&qh,  g_qh);   cudaGetSymbolAddress((void**)&ql,  g_ql);
    cudaGetSymbolAddress((void**)&kvh, g_kvh);  cudaGetSymbolAddress((void**)&kvl, g_kvl);
    cudaGetSymbolAddress((void**)&att, g_att);
    cudaGetSymbolAddress((void**)&wkvh, g_wkv_h); cudaGetSymbolAddress((void**)&wkvl, g_wkv_l);
    cudaGetSymbolAddress((void**)&wqh,  g_wq_h);  cudaGetSymbolAddress((void**)&wql,  g_wq_l);
    cudaGetSymbolAddress((void**)&wph,  g_wp_h);  cudaGetSymbolAddress((void**)&wpl,  g_wp_l);

    cudaFuncSetAttribute(gemm_tile<true>,  cudaFuncAttributeMaxDynamicSharedMemorySize, GEMM_SMEM);
    cudaFuncSetAttribute(gemm_tile<false>, cudaFuncAttributeMaxDynamicSharedMemorySize, GEMM_SMEM);
    cudaFuncSetAttribute(gemm_proj, cudaFuncAttributeMaxDynamicSharedMemorySize, PROJ_SMEM);
    cudaFuncSetAttribute(attn2,     cudaFuncAttributeMaxDynamicSharedMemorySize, ATTN_SMEM);

    const float cscale = 0.125f * 1.4426950408889634f;

    split_w<<<(512 * 1024 + 255) / 256, 256>>>(Wkv,   wkvh, wkvl, 512, 1024);
    split_w<<<(512 * 512  + 255) / 256, 256>>>(Wq,    wqh,  wql,  512, 512);
    split_w<<<(512 * 512  + 255) / 256, 256>>>(Wproj, wph,  wpl,  512, 512);

    // kv K-columns: 2-term specialization
    gemm_tile<true><<<dim3(2, 1024), 128, GEMM_SMEM>>>(
        x, query, wkvh, wkvl, wqh, wql, bkv, bq, kvh, kvl, qh, ql, cscale);
    // kv V-columns + q: 3-term specialization
    gemm_tile<false><<<dim3(2, 1056), 128, GEMM_SMEM>>>(
        x, query, wkvh, wkvl, wqh, wql, bkv, bq, kvh, kvl, qh, ql, cscale);
    // attention -> att fp32
    attn2<<<B_ * H_ * (L_ / 64), 128, ATTN_SMEM>>>(qh, ql, kvh, kvl, att);
    // out = att @ Wproj + bproj (128 CTAs, 2/SM)
    gemm_proj<<<dim3(D_ / 128, (B_ * L_) / 64), 128, PROJ_SMEM>>>(
        att, wph, wpl, bproj, out, B_ * L_, D_, D_);
}

// round 16
// speedup vs baseline: 1.0105x; 1.0105x over previous
#include <cuda_runtime.h>
#include <cuda_bf16.h>
#include <math_constants.h>
#include <cstdint>

// Problem constants
#define B_ 8
#define T_ 8192
#define L_ 256
#define D_ 512
#define H_ 8
// HD = 64, scale = 1/8

// ---------------- scratch (device globals; no allocs allowed) ----------------
__device__ __nv_bfloat16 g_qh [(size_t)B_ * L_ * D_],  g_ql [(size_t)B_ * L_ * D_];
__device__ __nv_bfloat16 g_kvh[(size_t)B_ * T_ * 2 * D_], g_kvl[(size_t)B_ * T_ * 2 * D_];
__device__ float         g_att[(size_t)B_ * L_ * D_];

__device__ __nv_bfloat16 g_wkv_h[1024 * 512], g_wkv_l[1024 * 512];   // Wkv^T split
__device__ __nv_bfloat16 g_wq_h [512 * 512],  g_wq_l [512 * 512];    // Wq^T split
__device__ __nv_bfloat16 g_wp_h [512 * 512],  g_wp_l [512 * 512];    // Wproj^T split

__device__ __forceinline__ uint32_t smem_u32(const void* p) {
    uint32_t a;
    asm("{ .reg .u64 t; cvta.to.shared.u64 t, %1; cvt.u32.u64 %0, t; }"
        : "=r"(a) : "l"(p));
    return a;
}

#define CP16(dst, src) \
    asm volatile("cp.async.cg.shared.global [%0], [%1], 16;" :: "r"(dst), "l"(src))
#define CP_COMMIT() asm volatile("cp.async.commit_group;" ::: "memory")
#define CP_WAIT(n)  asm volatile("cp.async.wait_group %0;" :: "n"(n) : "memory")

#define LDSM4(r, addr) \
    asm volatile("ldmatrix.sync.aligned.m8n8.x4.shared.b16 {%0,%1,%2,%3}, [%4];" \
        : "=r"((r)[0]), "=r"((r)[1]), "=r"((r)[2]), "=r"((r)[3]) : "r"(addr))
#define LDSM4T(r, addr) \
    asm volatile("ldmatrix.sync.aligned.m8n8.x4.trans.shared.b16 {%0,%1,%2,%3}, [%4];" \
        : "=r"((r)[0]), "=r"((r)[1]), "=r"((r)[2]), "=r"((r)[3]) : "r"(addr))

#define MMA16816(d, a, b0r, b1r) \
    asm volatile("mma.sync.aligned.m16n8k16.row.col.f32.bf16.bf16.f32 " \
        "{%0,%1,%2,%3}, {%4,%5,%6,%7}, {%8,%9}, {%0,%1,%2,%3};" \
        : "+f"((d)[0]), "+f"((d)[1]), "+f"((d)[2]), "+f"((d)[3]) \
        : "r"((a)[0]), "r"((a)[1]), "r"((a)[2]), "r"((a)[3]), "r"(b0r), "r"(b1r))

#define SWZ64(o)  ((o) ^ ((((o) >> 7) & 3) << 4))
#define SWZ128(o) ((o) ^ ((((o) >> 7) & 7) << 4))

// =============================================================================
// Weight split/transpose: W[K,N] fp32 -> Wt_hi/Wt_lo [N,K] bf16
// =============================================================================
__global__ void split_w(const float* __restrict__ W, __nv_bfloat16* __restrict__ Th,
                        __nv_bfloat16* __restrict__ Tl, int K, int N)
{
    int idx = blockIdx.x * blockDim.x + threadIdx.x;
    if (idx >= K * N) return;
    int k = idx / N, n = idx % N;
    float w = W[idx];
    __nv_bfloat16 h = __float2bfloat16_rn(w);
    float r = w - __bfloat162float(h);
    Th[(size_t)n * K + k] = h;
    Tl[(size_t)n * K + k] = __float2bfloat16_rn(r);
}

// =============================================================================
// Fused kv+q GEMM (R13-proven, 520.6us): 128 threads / 4 warps, CTA 64x256,
// warp 64x64, 2 CTAs/SM. grid (4, 1056). kv K-cols (bx<2): 2-term, Ch only.
// B via 3-stage cp.async; A via LDG prefetch + split. smem 112KB.
// =============================================================================
#define GEMM_SMEM 114688

__global__ __launch_bounds__(128, 2)
void gemm_kvq(const float* __restrict__ x, const float* __restrict__ query,
              const __nv_bfloat16* __restrict__ wkvh, const __nv_bfloat16* __restrict__ wkvl,
              const __nv_bfloat16* __restrict__ wqh,  const __nv_bfloat16* __restrict__ wql,
              const float* __restrict__ bkv, const float* __restrict__ bq,
              __nv_bfloat16* __restrict__ kvh, __nv_bfloat16* __restrict__ kvl,
              __nv_bfloat16* __restrict__ qh,  __nv_bfloat16* __restrict__ ql,
              float cscale)
{
    const bool isQ = (blockIdx.y >= 1024);
    if (isQ && blockIdx.x >= 2) return;

    const float* A               = isQ ? query : x;
    const __nv_bfloat16* Bth     = isQ ? wqh : wkvh;
    const __nv_bfloat16* Btl     = isQ ? wql : wkvl;
    const float* bias            = isQ ? bq : bkv;
    __nv_bfloat16* Ch            = isQ ? qh : kvh;
    __nv_bfloat16* Cl            = isQ ? ql : kvl;
    const float scale            = isQ ? cscale : 1.0f;
    const int N                  = isQ ? 512 : 1024;
    const int K                  = 512;
    const int bm = (isQ ? (blockIdx.y - 1024) : blockIdx.y) * 64;
    const int bn = blockIdx.x * 256;
    const bool two_term = (!isQ) && (blockIdx.x < 2);   // kv K-columns

    extern __shared__ char smem[];
    const uint32_t sbase = smem_u32(smem);
    const int tid  = threadIdx.x;
    const int lane = tid & 31;
    const int wn   = tid >> 5;

    float acc[4][8][4];
    #pragma unroll
    for (int i = 0; i < 4; i++)
        #pragma unroll
        for (int j = 0; j < 8; j++)
            #pragma unroll
            for (int k = 0; k < 4; k++) acc[i][j][k] = 0.f;

    const int nchunk = K >> 5;

    auto produceB = [&](int c, int s) {
        const uint32_t base = sbase + 16384 + (uint32_t)s * 32768;
        #pragma unroll
        for (int i = 0; i < 8; i++) {
            int idx = tid + i * 128;
            int n = idx >> 2, sg = idx & 3;
            uint32_t sw = SWZ64(n * 64 + sg * 16);
            const size_t gb = (size_t)(bn + n) * K + c * 32 + sg * 8;
            CP16(base + sw,         Bth + gb);
            CP16(base + 16384 + sw, Btl + gb);
        }
    };

    float4 pa[4];
    auto loadA = [&](int c) {
        #pragma unroll
        for (int i = 0; i < 4; i++) {
            int idx = tid + i * 128;
            int r = idx >> 3, k4 = idx & 7;
            pa[i] = *reinterpret_cast<const float4*>(
                A + (size_t)(bm + r) * K + c * 32 + k4 * 4);
        }
    };
    auto storeA = [&](int buf) {
        char* base = smem + buf * 8192;
        #pragma unroll
        for (int i = 0; i < 4; i++) {
            int idx = tid + i * 128;
            int r = idx >> 3, k4 = idx & 7;
            uint32_t sw = SWZ64(r * 64 + k4 * 8);
            float4 v = pa[i];
            __nv_bfloat162 h01 = __floats2bfloat162_rn(v.x, v.y);
            __nv_bfloat162 h23 = __floats2bfloat162_rn(v.z, v.w);
            *reinterpret_cast<uint2*>(base + sw) =
                make_uint2(*(uint32_t*)&h01, *(uint32_t*)&h23);
            if (!two_term) {
                float2 f01 = __bfloat1622float2(h01);
                float2 f23 = __bfloat1622float2(h23);
                __nv_bfloat162 l01 = __floats2bfloat162_rn(v.x - f01.x, v.y - f01.y);
                __nv_bfloat162 l23 = __floats2bfloat162_rn(v.z - f23.x, v.w - f23.y);
                *reinterpret_cast<uint2*>(base + 4096 + sw) =
                    make_uint2(*(uint32_t*)&l01, *(uint32_t*)&l23);
            }
        }
    };

    const uint32_t arow  = (lane & 15);
    const uint32_t aoffb = arow * 64 + ((lane >> 4) << 4);
    const uint32_t axor  = ((arow >> 1) & 3) << 4;
    const uint32_t blrow = (lane & 7) + ((lane >> 4) << 3);
    const uint32_t bseg  = ((uint32_t)((lane >> 3) & 1)) << 4;

    auto compute = [&](int c) {
        const uint32_t sa = sbase + (uint32_t)(c & 1) * 8192;
        const uint32_t sbB = sbase + 16384 + (uint32_t)(c % 3) * 32768;
        #pragma unroll
        for (int ks = 0; ks < 2; ks++) {
            uint32_t Ah[4][4], Al[4][4];
            #pragma unroll
            for (int mt = 0; mt < 4; mt++) {
                uint32_t addr = (sa + aoffb + mt * 1024 + ks * 32) ^ axor;
                LDSM4(Ah[mt], addr);
                if (!two_term) LDSM4(Al[mt], addr + 4096);
            }
            #pragma unroll
            for (int np = 0; np < 4; np++) {
                const uint32_t brow = wn * 64 + np * 16 + blrow;
                uint32_t off = brow * 64 + bseg + ks * 32;
                uint32_t addr = sbB + (off ^ (((brow >> 1) & 3) << 4));
                uint32_t Bh[4], Bl[4];
                LDSM4(Bh, addr);
                LDSM4(Bl, addr + 16384);
                float* d;
                #pragma unroll
                for (int mt = 0; mt < 4; mt++) {
                    d = acc[mt][2 * np];     MMA16816(d, Ah[mt], Bh[0], Bh[1]);
                    d = acc[mt][2 * np + 1]; MMA16816(d, Ah[mt], Bh[2], Bh[3]);
                }
                #pragma unroll
                for (int mt = 0; mt < 4; mt++) {
                    d = acc[mt][2 * np];     MMA16816(d, Ah[mt], Bl[0], Bl[1]);
                    d = acc[mt][2 * np + 1]; MMA16816(d, Ah[mt], Bl[2], Bl[3]);
                }
                if (!two_term) {
                    #pragma unroll
                    for (int mt = 0; mt < 4; mt++) {
                        d = acc[mt][2 * np];     MMA16816(d, Al[mt], Bh[0], Bh[1]);
                        d = acc[mt][2 * np + 1]; MMA16816(d, Al[mt], Bh[2], Bh[3]);
                    }
                }
            }
        }
    };

    produceB(0, 0); CP_COMMIT();
    produceB(1, 1); CP_COMMIT();
    loadA(0);
    storeA(0);
    for (int c = 0; c < nchunk; c++) {
        CP_WAIT(1);
        __syncthreads();
        if (c + 1 < nchunk) loadA(c + 1);
        if (c + 2 < nchunk) { produceB(c + 2, (c + 2) % 3); CP_COMMIT(); }
        compute(c);
        if (c + 1 < nchunk) storeA((c + 1) & 1);
    }

    // ---- epilogue: bf16 hi/lo (Cl skipped for kv K-columns) ----
    #pragma unroll
    for (int nt = 0; nt < 8; nt++) {
        const int ncol = bn + wn * 64 + nt * 8 + 2 * (lane & 3);
        const float2 bb = *reinterpret_cast<const float2*>(bias + ncol);
        #pragma unroll
        for (int mt = 0; mt < 4; mt++) {
            const int m0 = bm + mt * 16 + (lane >> 2);
            float v0 = (acc[mt][nt][0] + bb.x) * scale;
            float v1 = (acc[mt][nt][1] + bb.y) * scale;
            float v2 = (acc[mt][nt][2] + bb.x) * scale;
            float v3 = (acc[mt][nt][3] + bb.y) * scale;
            __nv_bfloat162 h01 = __floats2bfloat162_rn(v0, v1);
            __nv_bfloat162 h23 = __floats2bfloat162_rn(v2, v3);
            *reinterpret_cast<uint32_t*>(Ch + (size_t)m0 * N + ncol) = *(uint32_t*)&h01;
            *reinterpret_cast<uint32_t*>(Ch + (size_t)(m0 + 8) * N + ncol) = *(uint32_t*)&h23;
            if (!two_term) {
                float2 f01 = __bfloat1622float2(h01);
                float2 f23 = __bfloat1622float2(h23);
                __nv_bfloat162 l01 = __floats2bfloat162_rn(v0 - f01.x, v1 - f01.y);
                __nv_bfloat162 l23 = __floats2bfloat162_rn(v2 - f23.x, v3 - f23.y);
                *reinterpret_cast<uint32_t*>(Cl + (size_t)m0 * N + ncol) = *(uint32_t*)&l01;
                *reinterpret_cast<uint32_t*>(Cl + (size_t)(m0 + 8) * N + ncol) = *(uint32_t*)&l23;
            }
        }
    }
}

// =============================================================================
// proj GEMM (R14): 64x128 CTA / 128 threads / 2 CTAs/SM. grid (4, 32).
// =============================================================================
#define PROJ_SMEM 49152

__global__ __launch_bounds__(128, 2)
void gemm_proj(const float* __restrict__ A,
               const __nv_bfloat16* __restrict__ Bth, const __nv_bfloat16* __restrict__ Btl,
               const float* __restrict__ bias, float* __restrict__ Cf,
               int M, int N, int K)
{
    extern __shared__ char smem[];
    const uint32_t sbase = smem_u32(smem);
    const int tid  = threadIdx.x;
    const int lane = tid & 31;
    const int wn   = tid >> 5;
    const int bm = blockIdx.y * 64;
    const int bn = blockIdx.x * 128;

    float acc[4][4][4];
    #pragma unroll
    for (int i = 0; i < 4; i++)
        #pragma unroll
        for (int j = 0; j < 4; j++)
            #pragma unroll
            for (int k = 0; k < 4; k++) acc[i][j][k] = 0.f;

    const int nchunk = K >> 5;
    float4 pa[4];
    uint4  pbh[4], pbl[4];

    auto loadg = [&](int c) {
        #pragma unroll
        for (int i = 0; i < 4; i++) {
            int idx = tid + i * 128;
            int r = idx >> 3, k4 = idx & 7;
            pa[i] = *reinterpret_cast<const float4*>(
                A + (size_t)(bm + r) * K + c * 32 + k4 * 4);
        }
        #pragma unroll
        for (int i = 0; i < 4; i++) {
            int idx = tid + i * 128;
            int n = idx >> 2, s = idx & 3;
            const size_t go = (size_t)(bn + n) * K + c * 32 + s * 8;
            pbh[i] = *reinterpret_cast<const uint4*>(Bth + go);
            pbl[i] = *reinterpret_cast<const uint4*>(Btl + go);
        }
    };

    auto storeS = [&](int buf) {
        char* base = smem + buf * 24576;
        #pragma unroll
        for (int i = 0; i < 4; i++) {
            int idx = tid + i * 128;
            int r = idx >> 3, k4 = idx & 7;
            uint32_t sw = SWZ64(r * 64 + k4 * 8);
            float4 v = pa[i];
            __nv_bfloat162 h01 = __floats2bfloat162_rn(v.x, v.y);
            __nv_bfloat162 h23 = __floats2bfloat162_rn(v.z, v.w);
            float2 f01 = __bfloat1622float2(h01);
            float2 f23 = __bfloat1622float2(h23);
            __nv_bfloat162 l01 = __floats2bfloat162_rn(v.x - f01.x, v.y - f01.y);
            __nv_bfloat162 l23 = __floats2bfloat162_rn(v.z - f23.x, v.w - f23.y);
            *reinterpret_cast<uint2*>(base + sw) =
                make_uint2(*(uint32_t*)&h01, *(uint32_t*)&h23);
            *reinterpret_cast<uint2*>(base + 4096 + sw) =
                make_uint2(*(uint32_t*)&l01, *(uint32_t*)&l23);
        }
        #pragma unroll
        for (int i = 0; i < 4; i++) {
            int idx = tid + i * 128;
            int n = idx >> 2, s = idx & 3;
            uint32_t sw = SWZ64(n * 64 + s * 16);
            *reinterpret_cast<uint4*>(base + 8192 + sw)  = pbh[i];
            *reinterpret_cast<uint4*>(base + 16384 + sw) = pbl[i];
        }
    };

    const uint32_t arow  = (lane & 15);
    const uint32_t aoffb = arow * 64 + ((lane >> 4) << 4);
    const uint32_t axor  = ((arow >> 1) & 3) << 4;
    const uint32_t brow  = wn * 32 + (lane & 7) + ((lane >> 4) << 3);
    const uint32_t boffb = brow * 64 + (((lane >> 3) & 1) << 4);
    const uint32_t bxor  = ((brow >> 1) & 3) << 4;

    auto compute = [&](int buf) {
        const uint32_t sa = sbase + buf * 24576;
        #pragma unroll
        for (int ks = 0; ks < 2; ks++) {
            uint32_t Ah[4][4], Al[4][4];
            #pragma unroll
            for (int mt = 0; mt < 4; mt++) {
                uint32_t addr = (sa + aoffb + mt * 1024 + ks * 32) ^ axor;
                LDSM4(Ah[mt], addr);
                LDSM4(Al[mt], addr + 4096);
            }
            uint32_t Bh[2][4], Bl[2][4];
            #pragma unroll
            for (int np = 0; np < 2; np++) {
                uint32_t addr = (sa + 8192 + boffb + np * 1024 + ks * 32) ^ bxor;
                LDSM4(Bh[np], addr);
                LDSM4(Bl[np], addr + 8192);
            }
            #pragma unroll
            for (int mt = 0; mt < 4; mt++)
                #pragma unroll
                for (int nt = 0; nt < 4; nt++) {
                    const int np = nt >> 1, bi = (nt & 1) * 2;
                    MMA16816(acc[mt][nt], Ah[mt], Bh[np][bi], Bh[np][bi + 1]);
                }
            #pragma unroll
            for (int mt = 0; mt < 4; mt++)
                #pragma unroll
                for (int nt = 0; nt < 4; nt++) {
                    const int np = nt >> 1, bi = (nt & 1) * 2;
                    MMA16816(acc[mt][nt], Ah[mt], Bl[np][bi], Bl[np][bi + 1]);
                }
            #pragma unroll
            for (int mt = 0; mt < 4; mt++)
                #pragma unroll
                for (int nt = 0; nt < 4; nt++) {
                    const int np = nt >> 1, bi = (nt & 1) * 2;
                    MMA16816(acc[mt][nt], Al[mt], Bh[np][bi], Bh[np][bi + 1]);
                }
        }
    };

    loadg(0);
    storeS(0);
    __syncthreads();
    for (int c = 0; c < nchunk; c++) {
        if (c + 1 < nchunk) loadg(c + 1);
        compute(c & 1);
        if (c + 1 < nchunk) {
            storeS((c + 1) & 1);
            __syncthreads();
        }
    }

    #pragma unroll
    for (int nt = 0; nt < 4; nt++) {
        const int ncol = bn + wn * 32 + nt * 8 + 2 * (lane & 3);
        const float2 bb = *reinterpret_cast<const float2*>(bias + ncol);
        #pragma unroll
        for (int mt = 0; mt < 4; mt++) {
            const int m0 = bm + mt * 16 + (lane >> 2);
            *reinterpret_cast<float2*>(Cf + (size_t)m0 * N + ncol) =
                make_float2(acc[mt][nt][0] + bb.x, acc[mt][nt][1] + bb.y);
            *reinterpret_cast<float2*>(Cf + (size_t)(m0 + 8) * N + ncol) =
                make_float2(acc[mt][nt][2] + bb.x, acc[mt][nt][3] + bb.y);
        }
    }
}

// =============================================================================
// HMMA flash attention (R13-proven): QK = (Qh+Ql)*Kh (2-term); PV = 3-term.
// 128 threads / 4 warps / 64 Q-rows; grid 256; 2 CTAs/SM.
// Stage 24KB (Kh|Vh|Vl) ring @0/24K/48K; Q hi @73728, lo @81920. smem = 88KB.
// =============================================================================
#define ATTN_SMEM 90112

__global__ __launch_bounds__(128, 2)
void attn2(const __nv_bfloat16* __restrict__ qsh, const __nv_bfloat16* __restrict__ qsl,
           const __nv_bfloat16* __restrict__ kvh, const __nv_bfloat16* __restrict__ kvl,
           float* __restrict__ attf)
{
    extern __shared__ char smem[];
    const uint32_t sb = smem_u32(smem);
    const int tid = threadIdx.x, lane = tid & 31, warp = tid >> 5;
    const int bid = blockIdx.x;
    const int lt = bid & 3;
    const int h  = (bid >> 2) & 7;
    const int b  = bid >> 5;
    const int l0 = lt * 64;

    #pragma unroll
    for (int i = 0; i < 4; i++) {
        int idx = tid + i * 128;
        int r = idx >> 3, sg = idx & 7;
        uint32_t sw = SWZ128(r * 128 + sg * 16);
        size_t g = (size_t)(b * L_ + l0 + r) * 512 + h * 64 + sg * 8;
        CP16(sb + 73728 + sw, qsh + g);
        CP16(sb + 81920 + sw, qsl + g);
    }
    CP_COMMIT();
    CP_WAIT(0);
    __syncthreads();

    uint32_t Qh[4][4], Ql[4][4];
    {
        const int arow = warp * 16 + (lane & 15);
        const uint32_t abase = sb + 73728 + arow * 128;
        const uint32_t axor = (arow & 7) << 4;
        #pragma unroll
        for (int kc = 0; kc < 4; kc++) {
            uint32_t o = ((((uint32_t)(lane >> 4) << 4) + kc * 32)) ^ axor;
            LDSM4(Qh[kc], abase + o);
            LDSM4(Ql[kc], abase + 8192 + o);
        }
    }
    __syncthreads();

    auto produce = [&](int c, int s) {
        const uint32_t base = sb + (uint32_t)s * 24576;
        #pragma unroll
        for (int i = 0; i < 4; i++) {
            int idx = tid + i * 128;
            int r = idx >> 3, sg = idx & 7;
            uint32_t sw = SWZ128(r * 128 + sg * 16);
            size_t g = (size_t)(b * T_ + c * 64 + r) * 1024 + h * 64 + sg * 8;
            CP16(base + sw,         kvh + g);
            CP16(base + 8192 + sw,  kvh + g + 512);
            CP16(base + 16384 + sw, kvl + g + 512);
        }
    };
    produce(0, 0); CP_COMMIT();
    produce(1, 1); CP_COMMIT();

    float mrow[2] = { -CUDART_INF_F, -CUDART_INF_F };
    float lsum[2] = { 0.f, 0.f };
    float O[8][4];
    #pragma unroll
    for (int i = 0; i < 8; i++)
        #pragma unroll
        for (int j = 0; j < 4; j++) O[i][j] = 0.f;

    const int klrow = (lane & 7) + ((lane >> 4) << 3);
    const uint32_t kseg = ((uint32_t)((lane >> 3) & 1)) << 4;
    const int vlrow = (lane & 7) + (((lane >> 3) & 1) << 3);
    const int vseg_half = lane >> 4;

    int bufc = 0;
    for (int c = 0; c < T_ / 64; c++) {
        CP_WAIT(1);
        __syncthreads();
        const uint32_t kb = sb + (uint32_t)bufc * 24576;

        float S[8][4];
        #pragma unroll
        for (int i = 0; i < 8; i++)
            #pragma unroll
            for (int j = 0; j < 4; j++) S[i][j] = 0.f;

        #pragma unroll
        for (int npp = 0; npp < 2; npp++) {
            #pragma unroll
            for (int kc = 0; kc < 4; kc++) {
                const int brow0 = (2 * npp) * 16 + klrow;
                const int brow1 = (2 * npp + 1) * 16 + klrow;
                uint32_t a0 = kb + brow0 * 128 + ((kseg + kc * 32) ^ ((brow0 & 7) << 4));
                uint32_t a1 = kb + brow1 * 128 + ((kseg + kc * 32) ^ ((brow1 & 7) << 4));
                uint32_t Bh0[4], Bh1[4];
                LDSM4(Bh0, a0);
                LDSM4(Bh1, a1);
                float* s0 = S[4 * npp];     float* s1 = S[4 * npp + 1];
                float* s2 = S[4 * npp + 2]; float* s3 = S[4 * npp + 3];
                MMA16816(s0, Qh[kc], Bh0[0], Bh0[1]);
                MMA16816(s1, Qh[kc], Bh0[2], Bh0[3]);
                MMA16816(s2, Qh[kc], Bh1[0], Bh1[1]);
                MMA16816(s3, Qh[kc], Bh1[2], Bh1[3]);
                MMA16816(s0, Ql[kc], Bh0[0], Bh0[1]);
                MMA16816(s1, Ql[kc], Bh0[2], Bh0[3]);
                MMA16816(s2, Ql[kc], Bh1[0], Bh1[1]);
                MMA16816(s3, Ql[kc], Bh1[2], Bh1[3]);
            }
        }

        float mxA = -CUDART_INF_F, mxB = -CUDART_INF_F;
        #pragma unroll
        for (int nt = 0; nt < 8; nt++) {
            mxA = fmaxf(mxA, fmaxf(S[nt][0], S[nt][1]));
            mxB = fmaxf(mxB, fmaxf(S[nt][2], S[nt][3]));
        }
        #pragma unroll
        for (int o = 1; o <= 2; o <<= 1) {
            mxA = fmaxf(mxA, __shfl_xor_sync(0xffffffffu, mxA, o));
            mxB = fmaxf(mxB, __shfl_xor_sync(0xffffffffu, mxB, o));
        }
        const float mnA = fmaxf(mrow[0], mxA);
        const float mnB = fmaxf(mrow[1], mxB);
        const float alphaA = exp2f(mrow[0] - mnA);
        const float alphaB = exp2f(mrow[1] - mnB);
        mrow[0] = mnA; mrow[1] = mnB;

        uint32_t Ph[4][4], Pl[4][4];
        float sumA = 0.f, sumB = 0.f;
        #pragma unroll
        for (int nt = 0; nt < 8; nt++) {
            float p0 = exp2f(S[nt][0] - mnA);
            float p1 = exp2f(S[nt][1] - mnA);
            float p2 = exp2f(S[nt][2] - mnB);
            float p3 = exp2f(S[nt][3] - mnB);
            sumA += p0 + p1; sumB += p2 + p3;
            __nv_bfloat162 hA = __floats2bfloat162_rn(p0, p1);
            __nv_bfloat162 hB = __floats2bfloat162_rn(p2, p3);
            float2 fA = __bfloat1622float2(hA);
            float2 fB = __bfloat1622float2(hB);
            __nv_bfloat162 lA = __floats2bfloat162_rn(p0 - fA.x, p1 - fA.y);
            __nv_bfloat162 lB = __floats2bfloat162_rn(p2 - fB.x, p3 - fB.y);
            const int kc = nt >> 1, ri = (nt & 1) * 2;
            Ph[kc][ri]     = *(uint32_t*)&hA;
            Ph[kc][ri + 1] = *(uint32_t*)&hB;
            Pl[kc][ri]     = *(uint32_t*)&lA;
            Pl[kc][ri + 1] = *(uint32_t*)&lB;
        }
        #pragma unroll
        for (int o = 1; o <= 2; o <<= 1) {
            sumA += __shfl_xor_sync(0xffffffffu, sumA, o);
            sumB += __shfl_xor_sync(0xffffffffu, sumB, o);
        }
        lsum[0] = lsum[0] * alphaA + sumA;
        lsum[1] = lsum[1] * alphaB + sumB;
        #pragma unroll
        for (int nt = 0; nt < 8; nt++) {
            O[nt][0] *= alphaA; O[nt][1] *= alphaA;
            O[nt][2] *= alphaB; O[nt][3] *= alphaB;
        }

        #pragma unroll
        for (int kc = 0; kc < 4; kc++) {
            const int vrow = kc * 16 + vlrow;
            const uint32_t vbase = kb + 8192 + vrow * 128;
            const uint32_t vxor = (vrow & 7) << 4;
            #pragma unroll
            for (int ngp = 0; ngp < 2; ngp++) {
                uint32_t o0 = ((uint32_t)((4 * ngp + vseg_half) << 4)) ^ vxor;
                uint32_t o1 = ((uint32_t)((4 * ngp + 2 + vseg_half) << 4)) ^ vxor;
                uint32_t Vh0[4], Vl0[4], Vh1[4], Vl1[4];
                LDSM4T(Vh0, vbase + o0); LDSM4T(Vl0, vbase + 8192 + o0);
                LDSM4T(Vh1, vbase + o1); LDSM4T(Vl1, vbase + 8192 + o1);
                float* d0 = O[4 * ngp];     float* d1 = O[4 * ngp + 1];
                float* d2 = O[4 * ngp + 2]; float* d3 = O[4 * ngp + 3];
                MMA16816(d0, Ph[kc], Vh0[0], Vh0[1]);
                MMA16816(d1, Ph[kc], Vh0[2], Vh0[3]);
                MMA16816(d2, Ph[kc], Vh1[0], Vh1[1]);
                MMA16816(d3, Ph[kc], Vh1[2], Vh1[3]);
                MMA16816(d0, Ph[kc], Vl0[0], Vl0[1]);
                MMA16816(d1, Ph[kc], Vl0[2], Vl0[3]);
                MMA16816(d2, Ph[kc], Vl1[0], Vl1[1]);
                MMA16816(d3, Ph[kc], Vl1[2], Vl1[3]);
                MMA16816(d0, Pl[kc], Vh0[0], Vh0[1]);
                MMA16816(d1, Pl[kc], Vh0[2], Vh0[3]);
                MMA16816(d2, Pl[kc], Vh1[0], Vh1[1]);
                MMA16816(d3, Pl[kc], Vh1[2], Vh1[3]);
            }
        }

        if (c + 2 < T_ / 64) produce(c + 2, (bufc + 2) % 3);
        CP_COMMIT();
        bufc = (bufc + 1) % 3;
    }
    CP_WAIT(0);

    const float invA = 1.0f / lsum[0];
    const float invB = 1.0f / lsum[1];
    const int rowA = b * L_ + l0 + warp * 16 + (lane >> 2);
    #pragma unroll
    for (int nt = 0; nt < 8; nt++) {
        const int col = h * 64 + nt * 8 + (lane & 3) * 2;
        *reinterpret_cast<float2*>(attf + (size_t)rowA * D_ + col) =
            make_float2(O[nt][0] * invA, O[nt][1] * invA);
        *reinterpret_cast<float2*>(attf + (size_t)(rowA + 8) * D_ + col) =
            make_float2(O[nt][2] * invB, O[nt][3] * invB);
    }
}

// =============================================================================
// launch
// =============================================================================
extern "C" void kernel_launch(void* const* d_in, const int* in_sizes, int n_in,
                              void* d_out, int out_size)
{
    const float* x     = (const float*)d_in[0];
    const float* query = (const float*)d_in[1];
    const float* Wq    = (const float*)d_in[2];
    const float* bq    = (const float*)d_in[3];
    const float* Wkv   = (const float*)d_in[4];
    const float* bkv   = (const float*)d_in[5];
    const float* Wproj = (const float*)d_in[6];
    const float* bproj = (const float*)d_in[7];
    float* out = (float*)d_out;

    __nv_bfloat16 *qh, *ql, *kvh, *kvl;
    float* att;
    __nv_bfloat16 *wkvh, *wkvl, *wqh, *wql, *wph, *wpl;
    cudaGetSymbolAddress((void**)&qh,  g_qh);   cudaGetSymbolAddress((void**)&ql,  g_ql);
    cudaGetSymbolAddress((void**)&kvh, g_kvh);  cudaGetSymbolAddress((void**)&kvl, g_kvl);
    cudaGetSymbolAddress((void**)&att, g_att);
    cudaGetSymbolAddress((void**)&wkvh, g_wkv_h); cudaGetSymbolAddress((void**)&wkvl, g_wkv_l);
    cudaGetSymbolAddress((void**)&wqh,  g_wq_h);  cudaGetSymbolAddress((void**)&wql,  g_wq_l);
    cudaGetSymbolAddress((void**)&wph,  g_wp_h);  cudaGetSymbolAddress((void**)&wpl,  g_wp_l);

    cudaFuncSetAttribute(gemm_kvq,  cudaFuncAttributeMaxDynamicSharedMemorySize, GEMM_SMEM);
    cudaFuncSetAttribute(gemm_proj, cudaFuncAttributeMaxDynamicSharedMemorySize, PROJ_SMEM);
    cudaFuncSetAttribute(attn2,     cudaFuncAttributeMaxDynamicSharedMemorySize, ATTN_SMEM);

    const float cscale = 0.125f * 1.4426950408889634f;

    split_w<<<(512 * 1024 + 255) / 256, 256>>>(Wkv,   wkvh, wkvl, 512, 1024);
    split_w<<<(512 * 512  + 255) / 256, 256>>>(Wq,    wqh,  wql,  512, 512);
    split_w<<<(512 * 512  + 255) / 256, 256>>>(Wproj, wph,  wpl,  512, 512);

    // fused kv+q GEMM (R13-proven): 64x256 CTAs, 2 per SM
    gemm_kvq<<<dim3(4, 1056), 128, GEMM_SMEM>>>(
        x, query, wkvh, wkvl, wqh, wql, bkv, bq, kvh, kvl, qh, ql, cscale);
    // attention (2-term QK, R13-proven) -> att fp32
    attn2<<<B_ * H_ * (L_ / 64), 128, ATTN_SMEM>>>(qh, ql, kvh, kvl, att);
    // out = att @ Wproj + bproj (128 CTAs, 2/SM)
    gemm_proj<<<dim3(D_ / 128, (B_ * L_) / 64), 128, PROJ_SMEM>>>(
        att, wph, wpl, bproj, out, B_ * L_, D_, D_);
}